// round 7
// baseline (speedup 1.0000x reference)
#include <cuda_runtime.h>
#include <cuda_bf16.h>

// x: (1, 256, 512, 512) fp32 -> out: (1, 64, 512, 512), mean over groups of 4 channels.
// HW4 = 512*512/4 = 65536 float4 per channel plane.
// out[c][p] = 0.25 * (x[4c][p] + x[4c+1][p] + x[4c+2][p] + x[4c+3][p])
//
// Each thread produces 2 output float4s (same channel, plane split in halves)
// -> 8 independent front-batched LDG.128 (MLP_p1=8), streaming cache hints.

static constexpr int HW4 = (512 * 512) / 4;   // 65536
static constexpr int C_OUT = 64;
static constexpr int THREADS = 256;
static constexpr int HALF = HW4 / 2;          // 32768

__global__ __launch_bounds__(THREADS)
void spectral_blurrin_kernel(const float4* __restrict__ x,
                             float4* __restrict__ out) {
    const int p = blockIdx.x * THREADS + threadIdx.x;   // 0 .. HALF-1
    const int c = blockIdx.y;

    const float4* in0 = x + (long long)c * 4 * HW4;

    // 8 independent 128-bit streaming loads (front-batched by ptxas)
    const float4 a0 = __ldcs(in0 + p);
    const float4 b0 = __ldcs(in0 + HW4 + p);
    const float4 d0 = __ldcs(in0 + 2 * HW4 + p);
    const float4 e0 = __ldcs(in0 + 3 * HW4 + p);
    const float4 a1 = __ldcs(in0 + HALF + p);
    const float4 b1 = __ldcs(in0 + HW4 + HALF + p);
    const float4 d1 = __ldcs(in0 + 2 * HW4 + HALF + p);
    const float4 e1 = __ldcs(in0 + 3 * HW4 + HALF + p);

    float4 r0, r1;
    r0.x = (a0.x + b0.x + d0.x + e0.x) * 0.25f;
    r0.y = (a0.y + b0.y + d0.y + e0.y) * 0.25f;
    r0.z = (a0.z + b0.z + d0.z + e0.z) * 0.25f;
    r0.w = (a0.w + b0.w + d0.w + e0.w) * 0.25f;
    r1.x = (a1.x + b1.x + d1.x + e1.x) * 0.25f;
    r1.y = (a1.y + b1.y + d1.y + e1.y) * 0.25f;
    r1.z = (a1.z + b1.z + d1.z + e1.z) * 0.25f;
    r1.w = (a1.w + b1.w + d1.w + e1.w) * 0.25f;

    float4* o = out + (long long)c * HW4;
    __stcs(o + p, r0);
    __stcs(o + HALF + p, r1);
}

extern "C" void kernel_launch(void* const* d_in, const int* in_sizes, int n_in,
                              void* d_out, int out_size) {
    const float4* x = (const float4*)d_in[0];
    float4* out = (float4*)d_out;

    dim3 grid(HALF / THREADS, C_OUT);   // (128, 64) = 8192 blocks
    spectral_blurrin_kernel<<<grid, THREADS>>>(x, out);
}

// round 9
// speedup vs baseline: 1.0316x; 1.0316x over previous
#include <cuda_runtime.h>
#include <cuda_bf16.h>

// x: (1, 256, 512, 512) fp32 -> out: (1, 64, 512, 512), mean over groups of 4 channels.
// HW4 = 512*512/4 = 65536 float4 per channel plane.
// out[c][p] = 0.25 * (x[4c][p] + x[4c+1][p] + x[4c+2][p] + x[4c+3][p])
//
// One output float4 per thread (MLP=4, the best-measured config), streaming
// cache hints (single-touch data), 512-thread blocks for DRAM row locality.

static constexpr int HW4 = (512 * 512) / 4;   // 65536
static constexpr int C_OUT = 64;
static constexpr int THREADS = 512;

__global__ __launch_bounds__(THREADS)
void spectral_blurrin_kernel(const float4* __restrict__ x,
                             float4* __restrict__ out) {
    const int p = blockIdx.x * THREADS + threadIdx.x;   // position within plane (float4 units)
    const int c = blockIdx.y;                           // output channel

    const float4* in0 = x + (long long)c * 4 * HW4 + p;

    // 4 independent 128-bit streaming loads, 1 MB apart -> front-batched, MLP=4
    const float4 a = __ldcs(in0);
    const float4 b = __ldcs(in0 + HW4);
    const float4 d = __ldcs(in0 + 2 * HW4);
    const float4 e = __ldcs(in0 + 3 * HW4);

    float4 r;
    r.x = (a.x + b.x + d.x + e.x) * 0.25f;
    r.y = (a.y + b.y + d.y + e.y) * 0.25f;
    r.z = (a.z + b.z + d.z + e.z) * 0.25f;
    r.w = (a.w + b.w + d.w + e.w) * 0.25f;

    __stcs(out + (long long)c * HW4 + p, r);
}

extern "C" void kernel_launch(void* const* d_in, const int* in_sizes, int n_in,
                              void* d_out, int out_size) {
    const float4* x = (const float4*)d_in[0];
    float4* out = (float4*)d_out;

    dim3 grid(HW4 / THREADS, C_OUT);   // (128, 64) = 8192 blocks
    spectral_blurrin_kernel<<<grid, THREADS>>>(x, out);
}